// round 2
// baseline (speedup 1.0000x reference)
#include <cuda_runtime.h>
#include <math.h>

// ---------------- problem constants ----------------
#define HH 512
#define WW 512
#define CC 96
#define HWSZ (HH * WW)            // 262144
#define WIN 8
#define SHIFT 4
#define NTOK 64                   // tokens per window
#define NWIN 4096                 // (512/8)^2
#define HEADS 6
#define HD 16
#define MLPH 384
#define EPS 1e-5f

// ---------------- scratch (device globals; no allocs allowed) ----------------
__device__ float g_xw[NWIN * NTOK * CC];   // LN1'd, shifted, windowed tokens [win][tok][96]
__device__ float g_y[NWIN * NTOK * CC];    // attention+proj output, windowed layout
__device__ float g_x1[HWSZ * CC];          // residual-1, [h*512+w][96]
__device__ float g_hn[HWSZ * CC];          // LN2 output, [h*512+w][96]

// ============================================================================
// Kernel A: transpose-read NCHW + LayerNorm1 + cyclic shift + window partition
// grid (8, 512), block 64. Tile: one h row, 64 w pixels.
// ============================================================================
__global__ void k_ln1_window(const float* __restrict__ x,
                             const float* __restrict__ n1w,
                             const float* __restrict__ n1b) {
    __shared__ float s[CC * 65];
    const int h = blockIdx.y;
    const int w0 = blockIdx.x * 64;
    const int t = threadIdx.x;

    // coalesced load: for each channel, 64 consecutive w
    #pragma unroll 4
    for (int c = 0; c < CC; ++c)
        s[c * 65 + t] = x[c * HWSZ + h * WW + w0 + t];
    __syncthreads();

    // per-pixel LayerNorm over 96 channels
    float mu = 0.f;
    #pragma unroll 8
    for (int c = 0; c < CC; ++c) mu += s[c * 65 + t];
    mu *= (1.0f / CC);
    float var = 0.f;
    #pragma unroll 8
    for (int c = 0; c < CC; ++c) { float d = s[c * 65 + t] - mu; var += d * d; }
    var *= (1.0f / CC);
    const float rstd = rsqrtf(var + EPS);
    #pragma unroll 8
    for (int c = 0; c < CC; ++c)
        s[c * 65 + t] = (s[c * 65 + t] - mu) * rstd * n1w[c] + n1b[c];
    __syncthreads();

    // scatter to windowed layout (apply shift): pixel (h,w) -> shifted (hs,ws)
    for (int idx = t; idx < 64 * CC; idx += 64) {
        const int tt = idx / CC, c = idx - tt * CC;
        const int wp = w0 + tt;
        const int hs = (h - SHIFT) & (HH - 1);
        const int ws = (wp - SHIFT) & (WW - 1);
        const int win = (hs >> 3) * 64 + (ws >> 3);
        const int tok = ((hs & 7) << 3) + (ws & 7);
        g_xw[(win * NTOK + tok) * CC + c] = s[c * 65 + tt];
    }
}

// ============================================================================
// Kernel C: per-window fused attention. One block per window (4096 blocks).
// smem: xin[64*97] | qk[64*291] | sa[64*65]  = 115968 B dynamic
// ============================================================================
__global__ void k_attn(const float* __restrict__ qkv_w,
                       const float* __restrict__ qkv_b,
                       const float* __restrict__ rpb,
                       const float* __restrict__ proj_w,
                       const float* __restrict__ proj_b) {
    extern __shared__ float smem[];
    float* xin = smem;                 // [64][97]
    float* qk  = smem + 64 * 97;       // [64][291] : q 0..95, k 96..191, v 192..287
    float* sa  = smem + 64 * 97 + 64 * 291;  // [64][65]

    const int win = blockIdx.x;
    const int tid = threadIdx.x;

    // 1. load window tokens
    for (int idx = tid; idx < NTOK * CC; idx += 256) {
        const int tok = idx / CC, c = idx - tok * CC;
        xin[tok * 97 + c] = g_xw[win * (NTOK * CC) + idx];
    }
    __syncthreads();

    // 2. qkv GEMM: [64 tok] x [288 r], 4x4 register tiles
    for (int g = tid; g < 16 * 72; g += 256) {
        const int t0 = (g & 15) * 4;
        const int r0 = (g >> 4) * 4;
        float acc[4][4];
        #pragma unroll
        for (int i = 0; i < 4; ++i)
            #pragma unroll
            for (int j = 0; j < 4; ++j) acc[i][j] = 0.f;
        #pragma unroll 4
        for (int c = 0; c < CC; ++c) {
            float xv[4], wv[4];
            #pragma unroll
            for (int i = 0; i < 4; ++i) xv[i] = xin[(t0 + i) * 97 + c];
            #pragma unroll
            for (int j = 0; j < 4; ++j) wv[j] = qkv_w[(r0 + j) * CC + c];
            #pragma unroll
            for (int i = 0; i < 4; ++i)
                #pragma unroll
                for (int j = 0; j < 4; ++j) acc[i][j] += xv[i] * wv[j];
        }
        #pragma unroll
        for (int i = 0; i < 4; ++i)
            #pragma unroll
            for (int j = 0; j < 4; ++j)
                qk[(t0 + i) * 291 + r0 + j] = acc[i][j] + qkv_b[r0 + j];
    }
    __syncthreads();

    const int wi = win >> 6, wj = win & 63;

    // 3. per-head attention
    for (int hd = 0; hd < HEADS; ++hd) {
        const int qo = hd * HD, ko = CC + hd * HD, vo = 2 * CC + hd * HD;

        // S = (q*scale) k^T + bias + mask
        for (int idx = tid; idx < NTOK * NTOK; idx += 256) {
            const int n = idx >> 6, m = idx & 63;
            const float* qn = qk + n * 291 + qo;
            const float* km = qk + m * 291 + ko;
            float acc = 0.f;
            #pragma unroll
            for (int d = 0; d < HD; ++d) acc += qn[d] * km[d];
            acc *= 0.25f;
            const int r1 = n >> 3, c1 = n & 7, r2 = m >> 3, c2 = m & 7;
            acc += rpb[((r1 - r2 + 7) * 15 + (c1 - c2 + 7)) * HEADS + hd];
            // shifted-window mask
            const int rgn = (wi == 63) ? (r1 < SHIFT ? 1 : 2) : 0;
            const int cgn = (wj == 63) ? (c1 < SHIFT ? 1 : 2) : 0;
            const int rgm = (wi == 63) ? (r2 < SHIFT ? 1 : 2) : 0;
            const int cgm = (wj == 63) ? (c2 < SHIFT ? 1 : 2) : 0;
            if (rgn * 3 + cgn != rgm * 3 + cgm) acc -= 100.0f;
            sa[n * 65 + m] = acc;
        }
        __syncthreads();

        // softmax per row
        if (tid < NTOK) {
            float* row = sa + tid * 65;
            float mx = -1e30f;
            #pragma unroll 8
            for (int m = 0; m < NTOK; ++m) mx = fmaxf(mx, row[m]);
            float sum = 0.f;
            #pragma unroll 8
            for (int m = 0; m < NTOK; ++m) { float e = __expf(row[m] - mx); row[m] = e; sum += e; }
            const float inv = 1.0f / sum;
            #pragma unroll 8
            for (int m = 0; m < NTOK; ++m) row[m] *= inv;
        }
        __syncthreads();

        // out = P @ v -> attnout stored back into xin columns [hd*16 .. hd*16+15]
        for (int idx = tid; idx < NTOK * HD; idx += 256) {
            const int d = idx & 15, n = idx >> 4;
            const float* pr = sa + n * 65;
            float acc = 0.f;
            #pragma unroll 8
            for (int m = 0; m < NTOK; ++m) acc += pr[m] * qk[m * 291 + vo + d];
            xin[n * 97 + qo + d] = acc;
        }
        __syncthreads();
    }

    // 4. proj: [64 tok] x [96 r], 4x4 tiles, result staged in qk (padded 97)
    for (int g = tid; g < 16 * 24; g += 256) {
        const int t0 = (g & 15) * 4;
        const int r0 = (g >> 4) * 4;
        float acc[4][4];
        #pragma unroll
        for (int i = 0; i < 4; ++i)
            #pragma unroll
            for (int j = 0; j < 4; ++j) acc[i][j] = 0.f;
        #pragma unroll 4
        for (int c = 0; c < CC; ++c) {
            float xv[4], wv[4];
            #pragma unroll
            for (int i = 0; i < 4; ++i) xv[i] = xin[(t0 + i) * 97 + c];
            #pragma unroll
            for (int j = 0; j < 4; ++j) wv[j] = proj_w[(r0 + j) * CC + c];
            #pragma unroll
            for (int i = 0; i < 4; ++i)
                #pragma unroll
                for (int j = 0; j < 4; ++j) acc[i][j] += xv[i] * wv[j];
        }
        #pragma unroll
        for (int i = 0; i < 4; ++i)
            #pragma unroll
            for (int j = 0; j < 4; ++j)
                qk[(t0 + i) * 97 + r0 + j] = acc[i][j] + proj_b[r0 + j];
    }
    __syncthreads();

    // 5. coalesced write-out
    for (int idx = tid; idx < NTOK * CC; idx += 256) {
        const int tok = idx / CC, c = idx - tok * CC;
        g_y[win * (NTOK * CC) + idx] = qk[tok * 97 + c];
    }
}

// ============================================================================
// Kernel D: window reverse + un-shift + residual (x^T + y) + LayerNorm2
// grid (8, 512), block 64
// ============================================================================
__global__ void k_res_ln2(const float* __restrict__ x,
                          const float* __restrict__ n2w,
                          const float* __restrict__ n2b) {
    __shared__ float s[CC * 65];
    __shared__ float smu[64], srs[64];
    const int h = blockIdx.y;
    const int w0 = blockIdx.x * 64;
    const int t = threadIdx.x;

    #pragma unroll 4
    for (int c = 0; c < CC; ++c)
        s[c * 65 + t] = x[c * HWSZ + h * WW + w0 + t];
    __syncthreads();

    // gather attention output (windowed layout, shifted coords) and add
    for (int idx = t; idx < 64 * CC; idx += 64) {
        const int tt = idx / CC, c = idx - tt * CC;
        const int wp = w0 + tt;
        const int hs = (h - SHIFT) & (HH - 1);
        const int ws = (wp - SHIFT) & (WW - 1);
        const int base = (((hs >> 3) * 64 + (ws >> 3)) * NTOK + ((hs & 7) << 3) + (ws & 7)) * CC;
        s[c * 65 + tt] += g_y[base + c];
    }
    __syncthreads();

    // LN2 stats per pixel
    float mu = 0.f;
    #pragma unroll 8
    for (int c = 0; c < CC; ++c) mu += s[c * 65 + t];
    mu *= (1.0f / CC);
    float var = 0.f;
    #pragma unroll 8
    for (int c = 0; c < CC; ++c) { float d = s[c * 65 + t] - mu; var += d * d; }
    var *= (1.0f / CC);
    smu[t] = mu;
    srs[t] = rsqrtf(var + EPS);
    __syncthreads();

    // write x1 and hn, coalesced ([pixel][96] contiguous for consecutive w)
    for (int idx = t; idx < 64 * CC; idx += 64) {
        const int tt = idx / CC, c = idx - tt * CC;
        const float v = s[c * 65 + tt];
        const int p = h * WW + w0 + tt;
        g_x1[p * CC + c] = v;
        g_hn[p * CC + c] = (v - smu[tt]) * srs[tt] * n2w[c] + n2b[c];
    }
}

// ============================================================================
// Kernel E: MLP (96->384 GELU ->96) + residual + transpose to NCHW output
// 4096 blocks x 256 threads, 64 tokens per block.
// smem: hn_s[64*97] | t1[64*385] = 123392 B dynamic
// ============================================================================
__global__ void k_mlp(const float* __restrict__ fc1_w,
                      const float* __restrict__ fc1_b,
                      const float* __restrict__ fc2_w,
                      const float* __restrict__ fc2_b,
                      float* __restrict__ out) {
    extern __shared__ float smem[];
    float* hs_ = smem;                // [64][97]
    float* t1 = smem + 64 * 97;       // [64][385]

    const int p0 = blockIdx.x * 64;
    const int tid = threadIdx.x;

    for (int idx = tid; idx < 64 * CC; idx += 256) {
        const int tok = idx / CC, c = idx - tok * CC;
        hs_[tok * 97 + c] = g_hn[p0 * CC + idx];
    }
    __syncthreads();

    // GEMM1 + GELU: [64 tok] x [384 j], 4x4 tiles
    for (int g = tid; g < 16 * 96; g += 256) {
        const int t0 = (g & 15) * 4;
        const int j0 = (g >> 4) * 4;
        float acc[4][4];
        #pragma unroll
        for (int i = 0; i < 4; ++i)
            #pragma unroll
            for (int j = 0; j < 4; ++j) acc[i][j] = 0.f;
        #pragma unroll 4
        for (int c = 0; c < CC; ++c) {
            float xv[4], wv[4];
            #pragma unroll
            for (int i = 0; i < 4; ++i) xv[i] = hs_[(t0 + i) * 97 + c];
            #pragma unroll
            for (int j = 0; j < 4; ++j) wv[j] = fc1_w[(j0 + j) * CC + c];
            #pragma unroll
            for (int i = 0; i < 4; ++i)
                #pragma unroll
                for (int j = 0; j < 4; ++j) acc[i][j] += xv[i] * wv[j];
        }
        #pragma unroll
        for (int i = 0; i < 4; ++i)
            #pragma unroll
            for (int j = 0; j < 4; ++j) {
                const float v = acc[i][j] + fc1_b[j0 + j];
                t1[(t0 + i) * 385 + j0 + j] = 0.5f * v * (1.0f + erff(v * 0.70710678118654752f));
            }
    }
    __syncthreads();

    // GEMM2 + residual + NCHW store: [64 tok] x [96 r], 4x4 tiles
    for (int g = tid; g < 16 * 24; g += 256) {
        const int t0 = (g & 15) * 4;
        const int r0 = (g >> 4) * 4;
        float acc[4][4];
        #pragma unroll
        for (int i = 0; i < 4; ++i)
            #pragma unroll
            for (int j = 0; j < 4; ++j) acc[i][j] = 0.f;
        #pragma unroll 4
        for (int jj = 0; jj < MLPH; ++jj) {
            float xv[4], wv[4];
            #pragma unroll
            for (int i = 0; i < 4; ++i) xv[i] = t1[(t0 + i) * 385 + jj];
            #pragma unroll
            for (int j = 0; j < 4; ++j) wv[j] = fc2_w[(r0 + j) * MLPH + jj];
            #pragma unroll
            for (int i = 0; i < 4; ++i)
                #pragma unroll
                for (int j = 0; j < 4; ++j) acc[i][j] += xv[i] * wv[j];
        }
        #pragma unroll
        for (int i = 0; i < 4; ++i)
            #pragma unroll
            for (int j = 0; j < 4; ++j) {
                const int p = p0 + t0 + i;
                const int r = r0 + j;
                out[r * HWSZ + p] = acc[i][j] + fc2_b[r] + g_x1[p * CC + r];
            }
    }
}

// ============================================================================
extern "C" void kernel_launch(void* const* d_in, const int* in_sizes, int n_in,
                              void* d_out, int out_size) {
    const float* x      = (const float*)d_in[0];
    const float* n1w    = (const float*)d_in[1];
    const float* n1b    = (const float*)d_in[2];
    const float* qkv_w  = (const float*)d_in[3];
    const float* qkv_b  = (const float*)d_in[4];
    const float* rpb    = (const float*)d_in[5];
    const float* proj_w = (const float*)d_in[6];
    const float* proj_b = (const float*)d_in[7];
    const float* n2w    = (const float*)d_in[8];
    const float* n2b    = (const float*)d_in[9];
    const float* fc1_w  = (const float*)d_in[10];
    const float* fc1_b  = (const float*)d_in[11];
    const float* fc2_w  = (const float*)d_in[12];
    const float* fc2_b  = (const float*)d_in[13];
    float* out = (float*)d_out;

    static bool attr_set = false;
    cudaFuncSetAttribute(k_attn, cudaFuncAttributeMaxDynamicSharedMemorySize, 115968);
    cudaFuncSetAttribute(k_mlp,  cudaFuncAttributeMaxDynamicSharedMemorySize, 123392);
    (void)attr_set;

    k_ln1_window<<<dim3(8, 512), 64>>>(x, n1w, n1b);
    k_attn<<<NWIN, 256, 115968>>>(qkv_w, qkv_b, rpb, proj_w, proj_b);
    k_res_ln2<<<dim3(8, 512), 64>>>(x, n2w, n2b);
    k_mlp<<<NWIN, 256, 123392>>>(fc1_w, fc1_b, fc2_w, fc2_b, out);
}

// round 8
// speedup vs baseline: 1.6783x; 1.6783x over previous
#include <cuda_runtime.h>
#include <math.h>

// ---------------- problem constants ----------------
#define HH 512
#define WW 512
#define CC 96
#define HWSZ (HH * WW)            // 262144
#define WIN 8
#define SHIFT 4
#define NTOK 64
#define NWIN 4096
#define HEADS 6
#define HD 16
#define MLPH 384
#define EPS 1e-5f

__device__ __forceinline__ float4 ld4s(const float* p) {
    return *reinterpret_cast<const float4*>(p);
}

// ---------------- scratch ----------------
__device__ float g_xw[NWIN * NTOK * CC];   // LN1'd, shifted, windowed tokens [win][tok][96]
__device__ float g_y[NWIN * NTOK * CC];    // attention+proj output [win][tok][96]
__device__ float g_x1T[CC * HWSZ];         // residual-1, TRANSPOSED [c][p]
__device__ float g_hnT[CC * HWSZ];         // LN2 output,  TRANSPOSED [c][p]

// ============================================================================
// Kernel A: NCHW read + LayerNorm1 + cyclic shift + window partition
// ============================================================================
__global__ void k_ln1_window(const float* __restrict__ x,
                             const float* __restrict__ n1w,
                             const float* __restrict__ n1b) {
    __shared__ float s[CC * 65];
    const int h = blockIdx.y;
    const int w0 = blockIdx.x * 64;
    const int t = threadIdx.x;

    #pragma unroll 4
    for (int c = 0; c < CC; ++c)
        s[c * 65 + t] = x[c * HWSZ + h * WW + w0 + t];
    __syncthreads();

    float mu = 0.f;
    #pragma unroll 8
    for (int c = 0; c < CC; ++c) mu += s[c * 65 + t];
    mu *= (1.0f / CC);
    float var = 0.f;
    #pragma unroll 8
    for (int c = 0; c < CC; ++c) { float d = s[c * 65 + t] - mu; var += d * d; }
    var *= (1.0f / CC);
    const float rstd = rsqrtf(var + EPS);
    #pragma unroll 8
    for (int c = 0; c < CC; ++c)
        s[c * 65 + t] = (s[c * 65 + t] - mu) * rstd * n1w[c] + n1b[c];
    __syncthreads();

    for (int idx = t; idx < 64 * CC; idx += 64) {
        const int tt = idx / CC, c = idx - tt * CC;
        const int wp = w0 + tt;
        const int hs = (h - SHIFT) & (HH - 1);
        const int ws = (wp - SHIFT) & (WW - 1);
        const int win = (hs >> 3) * 64 + (ws >> 3);
        const int tok = ((hs & 7) << 3) + (ws & 7);
        g_xw[(win * NTOK + tok) * CC + c] = s[c * 65 + tt];
    }
}

// ============================================================================
// Kernel C: per-window fused attention, scalar fp32 FMA, float4 loads.
// smem: xin/po[64][100] | qk[64][292] | sa[6][64][68] = 204800 B
// ============================================================================
__global__ __launch_bounds__(256, 1)
void k_attn(const float* __restrict__ qkv_w,
            const float* __restrict__ qkv_b,
            const float* __restrict__ rpb,
            const float* __restrict__ proj_w,
            const float* __restrict__ proj_b) {
    extern __shared__ float smem[];
    float* xin = smem;                 // [64][100]  (reused as po after PV)
    float* qk  = smem + 6400;          // [64][292]: q 0..95, k 96..191, v 192..287
    float* sa  = smem + 25088;         // [6][64][68]
    __shared__ int rg[64];

    const int win = blockIdx.x;
    const int tid = threadIdx.x;
    const int wi = win >> 6, wj = win & 63;

    const float* src = g_xw + win * (NTOK * CC);
    for (int i = tid; i < NTOK * CC; i += 256) {
        const int tok = i / 96, c = i - tok * 96;
        xin[tok * 100 + c] = src[i];
    }
    if (tid < 64) {
        const int r1 = tid >> 3, c1 = tid & 7;
        const int a = (wi == 63) ? (r1 < SHIFT ? 1 : 2) : 0;
        const int b = (wj == 63) ? (c1 < SHIFT ? 1 : 2) : 0;
        rg[tid] = a * 3 + b;
    }
    __syncthreads();

    // ---- qkv GEMM: 64x288, K=96. tile 8tok x 8r (288 tiles) ----
    for (int g = tid; g < 288; g += 256) {
        const int tt = g & 7;              // token rows tt + 8i
        const int r0 = (g >> 3) << 3;      // 0..280
        float acc[8][8];
        #pragma unroll
        for (int i = 0; i < 8; ++i)
            #pragma unroll
            for (int j = 0; j < 8; ++j) acc[i][j] = 0.f;
        #pragma unroll 2
        for (int c0 = 0; c0 < 96; c0 += 4) {
            float4 xv[8];
            #pragma unroll
            for (int i = 0; i < 8; ++i) xv[i] = ld4s(&xin[(tt + 8 * i) * 100 + c0]);
            #pragma unroll
            for (int j = 0; j < 8; ++j) {
                const float4 wv = ld4s(&qkv_w[(r0 + j) * 96 + c0]);
                #pragma unroll
                for (int i = 0; i < 8; ++i) {
                    acc[i][j] += xv[i].x * wv.x + xv[i].y * wv.y
                               + xv[i].z * wv.z + xv[i].w * wv.w;
                }
            }
        }
        const float4 b0 = ld4s(&qkv_b[r0]);
        const float4 b1 = ld4s(&qkv_b[r0 + 4]);
        #pragma unroll
        for (int i = 0; i < 8; ++i) {
            const int t = tt + 8 * i;
            *reinterpret_cast<float4*>(&qk[t * 292 + r0]) =
                make_float4(acc[i][0] + b0.x, acc[i][1] + b0.y, acc[i][2] + b0.z, acc[i][3] + b0.w);
            *reinterpret_cast<float4*>(&qk[t * 292 + r0 + 4]) =
                make_float4(acc[i][4] + b1.x, acc[i][5] + b1.y, acc[i][6] + b1.z, acc[i][7] + b1.w);
        }
    }
    __syncthreads();

    // ---- S = q k^T * scale + bias + mask, all heads.
    //      tile 4n x 8m, n lane-major (q 2-way banks, k broadcast). 768 tiles ----
    for (int g = tid; g < 768; g += 256) {
        const int h = g >> 7;              // 0..5
        const int rem = g & 127;
        const int n0 = rem & 15;           // n rows n0 + 16i
        const int m0 = (rem >> 4) << 3;    // 0..56
        const int qo = h * 16, ko = 96 + h * 16;
        float qv[4][16];
        #pragma unroll
        for (int i = 0; i < 4; ++i) {
            #pragma unroll
            for (int k = 0; k < 4; ++k) {
                const float4 v = ld4s(&qk[(n0 + 16 * i) * 292 + qo + 4 * k]);
                qv[i][4 * k] = v.x; qv[i][4 * k + 1] = v.y;
                qv[i][4 * k + 2] = v.z; qv[i][4 * k + 3] = v.w;
            }
        }
        float acc[4][8];
        #pragma unroll
        for (int i = 0; i < 4; ++i)
            #pragma unroll
            for (int j = 0; j < 8; ++j) acc[i][j] = 0.f;
        #pragma unroll
        for (int j = 0; j < 8; ++j) {
            float kv[16];
            #pragma unroll
            for (int k = 0; k < 4; ++k) {
                const float4 v = ld4s(&qk[(m0 + j) * 292 + ko + 4 * k]);
                kv[4 * k] = v.x; kv[4 * k + 1] = v.y;
                kv[4 * k + 2] = v.z; kv[4 * k + 3] = v.w;
            }
            #pragma unroll
            for (int i = 0; i < 4; ++i) {
                float a = 0.f;
                #pragma unroll
                for (int d = 0; d < 16; ++d) a += qv[i][d] * kv[d];
                acc[i][j] = a;
            }
        }
        #pragma unroll
        for (int i = 0; i < 4; ++i) {
            const int n = n0 + 16 * i;
            const int r1 = n >> 3, c1 = n & 7;
            const int rgn = rg[n];
            float vo[8];
            #pragma unroll
            for (int j = 0; j < 8; ++j) {
                const int m = m0 + j;
                const int r2 = m >> 3, c2 = m & 7;
                float s = acc[i][j] * 0.25f
                        + rpb[((r1 - r2 + 7) * 15 + (c1 - c2 + 7)) * HEADS + h];
                if (rgn != rg[m]) s -= 100.0f;
                vo[j] = s;
            }
            *reinterpret_cast<float4*>(&sa[(h * 64 + n) * 68 + m0]) =
                make_float4(vo[0], vo[1], vo[2], vo[3]);
            *reinterpret_cast<float4*>(&sa[(h * 64 + n) * 68 + m0 + 4]) =
                make_float4(vo[4], vo[5], vo[6], vo[7]);
        }
    }
    __syncthreads();

    // ---- softmax: 384 rows ----
    for (int r = tid; r < 384; r += 256) {
        float* row = sa + r * 68;
        float mx = -1e30f;
        #pragma unroll
        for (int m = 0; m < 64; m += 4) {
            float4 v = *reinterpret_cast<float4*>(&row[m]);
            mx = fmaxf(mx, fmaxf(fmaxf(v.x, v.y), fmaxf(v.z, v.w)));
        }
        float sum = 0.f;
        #pragma unroll
        for (int m = 0; m < 64; m += 4) {
            float4 v = *reinterpret_cast<float4*>(&row[m]);
            v.x = __expf(v.x - mx); v.y = __expf(v.y - mx);
            v.z = __expf(v.z - mx); v.w = __expf(v.w - mx);
            sum += v.x + v.y + v.z + v.w;
            *reinterpret_cast<float4*>(&row[m]) = v;
        }
        const float inv = 1.0f / sum;
        #pragma unroll
        for (int m = 0; m < 64; m += 4) {
            float4 v = *reinterpret_cast<float4*>(&row[m]);
            v.x *= inv; v.y *= inv; v.z *= inv; v.w *= inv;
            *reinterpret_cast<float4*>(&row[m]) = v;
        }
    }
    __syncthreads();

    // ---- PV: out[n][d] = sum_m P[n][m] V[m][d]. tile 4n x 8d per head (192 tiles) ----
    float* po = xin;   // reuse
    if (tid < 192) {
        const int h = tid / 32;
        const int rem = tid & 31;
        const int n0 = rem & 15;           // n rows n0 + 16i
        const int d0 = (rem >> 4) << 3;    // 0 or 8
        const int vofs = 192 + h * 16 + d0;
        float acc[4][8];
        #pragma unroll
        for (int i = 0; i < 4; ++i)
            #pragma unroll
            for (int j = 0; j < 8; ++j) acc[i][j] = 0.f;
        for (int m0 = 0; m0 < 64; m0 += 4) {
            float p4[4][4];
            #pragma unroll
            for (int i = 0; i < 4; ++i) {
                const float4 u = ld4s(&sa[(h * 64 + n0 + 16 * i) * 68 + m0]);
                p4[i][0] = u.x; p4[i][1] = u.y; p4[i][2] = u.z; p4[i][3] = u.w;
            }
            #pragma unroll
            for (int mi = 0; mi < 4; ++mi) {
                const float4 v0 = ld4s(&qk[(m0 + mi) * 292 + vofs]);
                const float4 v1 = ld4s(&qk[(m0 + mi) * 292 + vofs + 4]);
                #pragma unroll
                for (int i = 0; i < 4; ++i) {
                    const float p = p4[i][mi];
                    acc[i][0] += p * v0.x; acc[i][1] += p * v0.y;
                    acc[i][2] += p * v0.z; acc[i][3] += p * v0.w;
                    acc[i][4] += p * v1.x; acc[i][5] += p * v1.y;
                    acc[i][6] += p * v1.z; acc[i][7] += p * v1.w;
                }
            }
        }
        #pragma unroll
        for (int i = 0; i < 4; ++i) {
            float* dst = &po[(n0 + 16 * i) * 100 + h * 16 + d0];
            *reinterpret_cast<float4*>(dst) =
                make_float4(acc[i][0], acc[i][1], acc[i][2], acc[i][3]);
            *reinterpret_cast<float4*>(dst + 4) =
                make_float4(acc[i][4], acc[i][5], acc[i][6], acc[i][7]);
        }
    }
    __syncthreads();

    // ---- proj: 64x96, K=96. tile 4tok x 8r (192 tiles) ----
    if (tid < 192) {
        const int tt = tid & 15;           // token rows tt + 16i
        const int r0 = (tid >> 4) << 3;    // 0..88
        float acc[4][8];
        #pragma unroll
        for (int i = 0; i < 4; ++i)
            #pragma unroll
            for (int j = 0; j < 8; ++j) acc[i][j] = 0.f;
        #pragma unroll 2
        for (int c0 = 0; c0 < 96; c0 += 4) {
            float4 xv[4];
            #pragma unroll
            for (int i = 0; i < 4; ++i) xv[i] = ld4s(&po[(tt + 16 * i) * 100 + c0]);
            #pragma unroll
            for (int j = 0; j < 8; ++j) {
                const float4 wv = ld4s(&proj_w[(r0 + j) * 96 + c0]);
                #pragma unroll
                for (int i = 0; i < 4; ++i) {
                    acc[i][j] += xv[i].x * wv.x + xv[i].y * wv.y
                               + xv[i].z * wv.z + xv[i].w * wv.w;
                }
            }
        }
        const float4 b0 = ld4s(&proj_b[r0]);
        const float4 b1 = ld4s(&proj_b[r0 + 4]);
        #pragma unroll
        for (int i = 0; i < 4; ++i) {
            const int t = tt + 16 * i;
            float* dst = &g_y[(win * 64 + t) * 96 + r0];
            *reinterpret_cast<float4*>(dst) =
                make_float4(acc[i][0] + b0.x, acc[i][1] + b0.y, acc[i][2] + b0.z, acc[i][3] + b0.w);
            *reinterpret_cast<float4*>(dst + 4) =
                make_float4(acc[i][4] + b1.x, acc[i][5] + b1.y, acc[i][6] + b1.z, acc[i][7] + b1.w);
        }
    }
}

// ============================================================================
// Kernel D: window reverse + un-shift + residual + LayerNorm2 -> transposed out
// ============================================================================
__global__ void k_res_ln2(const float* __restrict__ x,
                          const float* __restrict__ n2w,
                          const float* __restrict__ n2b) {
    __shared__ float s[CC * 65];
    const int h = blockIdx.y;
    const int w0 = blockIdx.x * 64;
    const int t = threadIdx.x;

    #pragma unroll 4
    for (int c = 0; c < CC; ++c)
        s[c * 65 + t] = x[c * HWSZ + h * WW + w0 + t];
    __syncthreads();

    for (int idx = t; idx < 64 * CC; idx += 64) {
        const int tt = idx / CC, c = idx - tt * CC;
        const int wp = w0 + tt;
        const int hs = (h - SHIFT) & (HH - 1);
        const int ws = (wp - SHIFT) & (WW - 1);
        const int base = (((hs >> 3) * 64 + (ws >> 3)) * NTOK + ((hs & 7) << 3) + (ws & 7)) * CC;
        s[c * 65 + tt] += g_y[base + c];
    }
    __syncthreads();

    float mu = 0.f;
    #pragma unroll 8
    for (int c = 0; c < CC; ++c) mu += s[c * 65 + t];
    mu *= (1.0f / CC);
    float var = 0.f;
    #pragma unroll 8
    for (int c = 0; c < CC; ++c) { float d = s[c * 65 + t] - mu; var += d * d; }
    var *= (1.0f / CC);
    const float rstd = rsqrtf(var + EPS);

    const int p = h * WW + w0 + t;
    #pragma unroll 4
    for (int c = 0; c < CC; ++c) {
        const float v = s[c * 65 + t];
        g_x1T[c * HWSZ + p] = v;
        g_hnT[c * HWSZ + p] = (v - mu) * rstd * n2w[c] + n2b[c];
    }
}

// ============================================================================
// Kernel E: MLP + residual + NCHW output. 384 threads.
// smem: xs[64][100] | t1[64][388] = 124928 B
// ============================================================================
__global__ __launch_bounds__(384, 1)
void k_mlp(const float* __restrict__ fc1_w,
           const float* __restrict__ fc1_b,
           const float* __restrict__ fc2_w,
           const float* __restrict__ fc2_b,
           float* __restrict__ out) {
    extern __shared__ float smem[];
    float* xs = smem;            // [64][100]
    float* t1 = smem + 6400;     // [64][388]
    const int p0 = blockIdx.x * 64;
    const int tid = threadIdx.x;

    for (int i = tid; i < 6144; i += 384) {
        const int c = i >> 6, t = i & 63;
        xs[t * 100 + c] = g_hnT[c * HWSZ + p0 + t];
    }
    __syncthreads();

    // ---- GEMM1 + GELU: 64x384, K=96. tile 8t x 8j (384 tiles, 1 pass) ----
    {
        const int tt = tid & 7;            // token rows tt + 8i
        const int j0 = (tid >> 3) << 3;    // 0..376
        float acc[8][8];
        #pragma unroll
        for (int i = 0; i < 8; ++i)
            #pragma unroll
            for (int j = 0; j < 8; ++j) acc[i][j] = 0.f;
        #pragma unroll 2
        for (int c0 = 0; c0 < 96; c0 += 4) {
            float4 xv[8];
            #pragma unroll
            for (int i = 0; i < 8; ++i) xv[i] = ld4s(&xs[(tt + 8 * i) * 100 + c0]);
            #pragma unroll
            for (int j = 0; j < 8; ++j) {
                const float4 wv = ld4s(&fc1_w[(j0 + j) * 96 + c0]);
                #pragma unroll
                for (int i = 0; i < 8; ++i) {
                    acc[i][j] += xv[i].x * wv.x + xv[i].y * wv.y
                               + xv[i].z * wv.z + xv[i].w * wv.w;
                }
            }
        }
        const float4 b0 = ld4s(&fc1_b[j0]);
        const float4 b1 = ld4s(&fc1_b[j0 + 4]);
        const float bb[8] = {b0.x, b0.y, b0.z, b0.w, b1.x, b1.y, b1.z, b1.w};
        #pragma unroll
        for (int i = 0; i < 8; ++i) {
            const int t = tt + 8 * i;
            float vo[8];
            #pragma unroll
            for (int j = 0; j < 8; ++j) {
                const float v = acc[i][j] + bb[j];
                vo[j] = 0.5f * v * (1.0f + erff(v * 0.70710678118654752f));
            }
            *reinterpret_cast<float4*>(&t1[t * 388 + j0]) =
                make_float4(vo[0], vo[1], vo[2], vo[3]);
            *reinterpret_cast<float4*>(&t1[t * 388 + j0 + 4]) =
                make_float4(vo[4], vo[5], vo[6], vo[7]);
        }
    }
    __syncthreads();

    // ---- GEMM2 + residual + NCHW store: 64x96, K=384. tile 4t x 4r (384 tiles) ----
    {
        const int tt = tid & 15;           // token rows tt + 16i
        const int r0 = (tid >> 4) << 2;    // 0..92
        float acc[4][4];
        #pragma unroll
        for (int i = 0; i < 4; ++i)
            #pragma unroll
            for (int j = 0; j < 4; ++j) acc[i][j] = 0.f;
        #pragma unroll 2
        for (int c0 = 0; c0 < MLPH; c0 += 4) {
            float4 xv[4];
            #pragma unroll
            for (int i = 0; i < 4; ++i) xv[i] = ld4s(&t1[(tt + 16 * i) * 388 + c0]);
            #pragma unroll
            for (int j = 0; j < 4; ++j) {
                const float4 wv = ld4s(&fc2_w[(r0 + j) * MLPH + c0]);
                #pragma unroll
                for (int i = 0; i < 4; ++i) {
                    acc[i][j] += xv[i].x * wv.x + xv[i].y * wv.y
                               + xv[i].z * wv.z + xv[i].w * wv.w;
                }
            }
        }
        #pragma unroll
        for (int i = 0; i < 4; ++i) {
            const int p = p0 + tt + 16 * i;
            #pragma unroll
            for (int j = 0; j < 4; ++j) {
                const int r = r0 + j;
                out[r * HWSZ + p] = acc[i][j] + fc2_b[r] + g_x1T[r * HWSZ + p];
            }
        }
    }
}

// ============================================================================
extern "C" void kernel_launch(void* const* d_in, const int* in_sizes, int n_in,
                              void* d_out, int out_size) {
    const float* x      = (const float*)d_in[0];
    const float* n1w    = (const float*)d_in[1];
    const float* n1b    = (const float*)d_in[2];
    const float* qkv_w  = (const float*)d_in[3];
    const float* qkv_b  = (const float*)d_in[4];
    const float* rpb    = (const float*)d_in[5];
    const float* proj_w = (const float*)d_in[6];
    const float* proj_b = (const float*)d_in[7];
    const float* n2w    = (const float*)d_in[8];
    const float* n2b    = (const float*)d_in[9];
    const float* fc1_w  = (const float*)d_in[10];
    const float* fc1_b  = (const float*)d_in[11];
    const float* fc2_w  = (const float*)d_in[12];
    const float* fc2_b  = (const float*)d_in[13];
    float* out = (float*)d_out;

    cudaFuncSetAttribute(k_attn, cudaFuncAttributeMaxDynamicSharedMemorySize, 204800);
    cudaFuncSetAttribute(k_mlp,  cudaFuncAttributeMaxDynamicSharedMemorySize, 124928);

    k_ln1_window<<<dim3(8, 512), 64>>>(x, n1w, n1b);
    k_attn<<<NWIN, 256, 204800>>>(qkv_w, qkv_b, rpb, proj_w, proj_b);
    k_res_ln2<<<dim3(8, 512), 64>>>(x, n2w, n2b);
    k_mlp<<<NWIN, 384, 124928>>>(fc1_w, fc1_b, fc2_w, fc2_b, out);
}

// round 12
// speedup vs baseline: 2.2505x; 1.3409x over previous
#include <cuda_runtime.h>
#include <cuda_bf16.h>
#include <math.h>

// ---------------- problem constants ----------------
#define HH 512
#define WW 512
#define CC 96
#define HWSZ (HH * WW)            // 262144
#define WIN 8
#define SHIFT 4
#define NTOK 64
#define NWIN 4096
#define HEADS 6
#define HD 16
#define MLPH 384
#define EPS 1e-5f

typedef unsigned int u32;

__device__ __forceinline__ float4 ld4s(const float* p) {
    return *reinterpret_cast<const float4*>(p);
}

// ---------------- scratch ----------------
__device__ float g_xw[NWIN * NTOK * CC];   // LN1'd, shifted, windowed tokens [win][tok][96]
__device__ float g_y[NWIN * NTOK * CC];    // attention+proj output [win][tok][96]
__device__ float g_x1T[CC * HWSZ];         // residual-1, TRANSPOSED [c][p]
__device__ float g_hnT[CC * HWSZ];         // LN2 output,  TRANSPOSED [c][p]

// ---------------- bf16 split helpers ----------------
__device__ __forceinline__ void bf16_split(float v, unsigned short& h, unsigned short& l) {
    __nv_bfloat16 hb = __float2bfloat16(v);
    __nv_bfloat16 lb = __float2bfloat16(v - __bfloat162float(hb));
    h = __bfloat16_as_ushort(hb);
    l = __bfloat16_as_ushort(lb);
}
__device__ __forceinline__ u32 pack2(unsigned short a, unsigned short b) {
    return (u32)a | ((u32)b << 16);
}

// mma.sync m16n8k16 bf16 (baseline sm_80+ instruction; valid for sm_103 target)
__device__ __forceinline__ void mma_bf16(float* c, u32 a0, u32 a1, u32 a2, u32 a3,
                                         u32 b0, u32 b1) {
    asm volatile(
        "mma.sync.aligned.m16n8k16.row.col.f32.bf16.bf16.f32 "
        "{%0,%1,%2,%3}, {%4,%5,%6,%7}, {%8,%9}, {%0,%1,%2,%3};"
        : "+f"(c[0]), "+f"(c[1]), "+f"(c[2]), "+f"(c[3])
        : "r"(a0), "r"(a1), "r"(a2), "r"(a3), "r"(b0), "r"(b1));
}

// ============================================================================
// Kernel A: NCHW read + LayerNorm1 + cyclic shift + window partition
// ============================================================================
__global__ void k_ln1_window(const float* __restrict__ x,
                             const float* __restrict__ n1w,
                             const float* __restrict__ n1b) {
    __shared__ float s[CC * 65];
    const int h = blockIdx.y;
    const int w0 = blockIdx.x * 64;
    const int t = threadIdx.x;

    #pragma unroll 4
    for (int c = 0; c < CC; ++c)
        s[c * 65 + t] = x[c * HWSZ + h * WW + w0 + t];
    __syncthreads();

    float mu = 0.f;
    #pragma unroll 8
    for (int c = 0; c < CC; ++c) mu += s[c * 65 + t];
    mu *= (1.0f / CC);
    float var = 0.f;
    #pragma unroll 8
    for (int c = 0; c < CC; ++c) { float d = s[c * 65 + t] - mu; var += d * d; }
    var *= (1.0f / CC);
    const float rstd = rsqrtf(var + EPS);
    #pragma unroll 8
    for (int c = 0; c < CC; ++c)
        s[c * 65 + t] = (s[c * 65 + t] - mu) * rstd * n1w[c] + n1b[c];
    __syncthreads();

    for (int idx = t; idx < 64 * CC; idx += 64) {
        const int tt = idx / CC, c = idx - tt * CC;
        const int wp = w0 + tt;
        const int hs = (h - SHIFT) & (HH - 1);
        const int ws = (wp - SHIFT) & (WW - 1);
        const int win = (hs >> 3) * 64 + (ws >> 3);
        const int tok = ((hs & 7) << 3) + (ws & 7);
        g_xw[(win * NTOK + tok) * CC + c] = s[c * 65 + tt];
    }
}

// ============================================================================
// Kernel C: per-window fused attention (identical to passing R8 version)
// smem: xin/po[64][100] | qk[64][292] | sa[6][64][68] = 204800 B
// ============================================================================
__global__ __launch_bounds__(256, 1)
void k_attn(const float* __restrict__ qkv_w,
            const float* __restrict__ qkv_b,
            const float* __restrict__ rpb,
            const float* __restrict__ proj_w,
            const float* __restrict__ proj_b) {
    extern __shared__ float smem[];
    float* xin = smem;
    float* qk  = smem + 6400;
    float* sa  = smem + 25088;
    __shared__ int rg[64];

    const int win = blockIdx.x;
    const int tid = threadIdx.x;
    const int wi = win >> 6, wj = win & 63;

    const float* src = g_xw + win * (NTOK * CC);
    for (int i = tid; i < NTOK * CC; i += 256) {
        const int tok = i / 96, c = i - tok * 96;
        xin[tok * 100 + c] = src[i];
    }
    if (tid < 64) {
        const int r1 = tid >> 3, c1 = tid & 7;
        const int a = (wi == 63) ? (r1 < SHIFT ? 1 : 2) : 0;
        const int b = (wj == 63) ? (c1 < SHIFT ? 1 : 2) : 0;
        rg[tid] = a * 3 + b;
    }
    __syncthreads();

    for (int g = tid; g < 288; g += 256) {
        const int tt = g & 7;
        const int r0 = (g >> 3) << 3;
        float acc[8][8];
        #pragma unroll
        for (int i = 0; i < 8; ++i)
            #pragma unroll
            for (int j = 0; j < 8; ++j) acc[i][j] = 0.f;
        #pragma unroll 2
        for (int c0 = 0; c0 < 96; c0 += 4) {
            float4 xv[8];
            #pragma unroll
            for (int i = 0; i < 8; ++i) xv[i] = ld4s(&xin[(tt + 8 * i) * 100 + c0]);
            #pragma unroll
            for (int j = 0; j < 8; ++j) {
                const float4 wv = ld4s(&qkv_w[(r0 + j) * 96 + c0]);
                #pragma unroll
                for (int i = 0; i < 8; ++i) {
                    acc[i][j] += xv[i].x * wv.x + xv[i].y * wv.y
                               + xv[i].z * wv.z + xv[i].w * wv.w;
                }
            }
        }
        const float4 b0 = ld4s(&qkv_b[r0]);
        const float4 b1 = ld4s(&qkv_b[r0 + 4]);
        #pragma unroll
        for (int i = 0; i < 8; ++i) {
            const int t = tt + 8 * i;
            *reinterpret_cast<float4*>(&qk[t * 292 + r0]) =
                make_float4(acc[i][0] + b0.x, acc[i][1] + b0.y, acc[i][2] + b0.z, acc[i][3] + b0.w);
            *reinterpret_cast<float4*>(&qk[t * 292 + r0 + 4]) =
                make_float4(acc[i][4] + b1.x, acc[i][5] + b1.y, acc[i][6] + b1.z, acc[i][7] + b1.w);
        }
    }
    __syncthreads();

    for (int g = tid; g < 768; g += 256) {
        const int h = g >> 7;
        const int rem = g & 127;
        const int n0 = rem & 15;
        const int m0 = (rem >> 4) << 3;
        const int qo = h * 16, ko = 96 + h * 16;
        float qv[4][16];
        #pragma unroll
        for (int i = 0; i < 4; ++i) {
            #pragma unroll
            for (int k = 0; k < 4; ++k) {
                const float4 v = ld4s(&qk[(n0 + 16 * i) * 292 + qo + 4 * k]);
                qv[i][4 * k] = v.x; qv[i][4 * k + 1] = v.y;
                qv[i][4 * k + 2] = v.z; qv[i][4 * k + 3] = v.w;
            }
        }
        float acc[4][8];
        #pragma unroll
        for (int i = 0; i < 4; ++i)
            #pragma unroll
            for (int j = 0; j < 8; ++j) acc[i][j] = 0.f;
        #pragma unroll
        for (int j = 0; j < 8; ++j) {
            float kv[16];
            #pragma unroll
            for (int k = 0; k < 4; ++k) {
                const float4 v = ld4s(&qk[(m0 + j) * 292 + ko + 4 * k]);
                kv[4 * k] = v.x; kv[4 * k + 1] = v.y;
                kv[4 * k + 2] = v.z; kv[4 * k + 3] = v.w;
            }
            #pragma unroll
            for (int i = 0; i < 4; ++i) {
                float a = 0.f;
                #pragma unroll
                for (int d = 0; d < 16; ++d) a += qv[i][d] * kv[d];
                acc[i][j] = a;
            }
        }
        #pragma unroll
        for (int i = 0; i < 4; ++i) {
            const int n = n0 + 16 * i;
            const int r1 = n >> 3, c1 = n & 7;
            const int rgn = rg[n];
            float vo[8];
            #pragma unroll
            for (int j = 0; j < 8; ++j) {
                const int m = m0 + j;
                const int r2 = m >> 3, c2 = m & 7;
                float s = acc[i][j] * 0.25f
                        + rpb[((r1 - r2 + 7) * 15 + (c1 - c2 + 7)) * HEADS + h];
                if (rgn != rg[m]) s -= 100.0f;
                vo[j] = s;
            }
            *reinterpret_cast<float4*>(&sa[(h * 64 + n) * 68 + m0]) =
                make_float4(vo[0], vo[1], vo[2], vo[3]);
            *reinterpret_cast<float4*>(&sa[(h * 64 + n) * 68 + m0 + 4]) =
                make_float4(vo[4], vo[5], vo[6], vo[7]);
        }
    }
    __syncthreads();

    for (int r = tid; r < 384; r += 256) {
        float* row = sa + r * 68;
        float mx = -1e30f;
        #pragma unroll
        for (int m = 0; m < 64; m += 4) {
            float4 v = *reinterpret_cast<float4*>(&row[m]);
            mx = fmaxf(mx, fmaxf(fmaxf(v.x, v.y), fmaxf(v.z, v.w)));
        }
        float sum = 0.f;
        #pragma unroll
        for (int m = 0; m < 64; m += 4) {
            float4 v = *reinterpret_cast<float4*>(&row[m]);
            v.x = __expf(v.x - mx); v.y = __expf(v.y - mx);
            v.z = __expf(v.z - mx); v.w = __expf(v.w - mx);
            sum += v.x + v.y + v.z + v.w;
            *reinterpret_cast<float4*>(&row[m]) = v;
        }
        const float inv = 1.0f / sum;
        #pragma unroll
        for (int m = 0; m < 64; m += 4) {
            float4 v = *reinterpret_cast<float4*>(&row[m]);
            v.x *= inv; v.y *= inv; v.z *= inv; v.w *= inv;
            *reinterpret_cast<float4*>(&row[m]) = v;
        }
    }
    __syncthreads();

    float* po = xin;
    if (tid < 192) {
        const int h = tid / 32;
        const int rem = tid & 31;
        const int n0 = rem & 15;
        const int d0 = (rem >> 4) << 3;
        const int vofs = 192 + h * 16 + d0;
        float acc[4][8];
        #pragma unroll
        for (int i = 0; i < 4; ++i)
            #pragma unroll
            for (int j = 0; j < 8; ++j) acc[i][j] = 0.f;
        for (int m0 = 0; m0 < 64; m0 += 4) {
            float p4[4][4];
            #pragma unroll
            for (int i = 0; i < 4; ++i) {
                const float4 u = ld4s(&sa[(h * 64 + n0 + 16 * i) * 68 + m0]);
                p4[i][0] = u.x; p4[i][1] = u.y; p4[i][2] = u.z; p4[i][3] = u.w;
            }
            #pragma unroll
            for (int mi = 0; mi < 4; ++mi) {
                const float4 v0 = ld4s(&qk[(m0 + mi) * 292 + vofs]);
                const float4 v1 = ld4s(&qk[(m0 + mi) * 292 + vofs + 4]);
                #pragma unroll
                for (int i = 0; i < 4; ++i) {
                    const float p = p4[i][mi];
                    acc[i][0] += p * v0.x; acc[i][1] += p * v0.y;
                    acc[i][2] += p * v0.z; acc[i][3] += p * v0.w;
                    acc[i][4] += p * v1.x; acc[i][5] += p * v1.y;
                    acc[i][6] += p * v1.z; acc[i][7] += p * v1.w;
                }
            }
        }
        #pragma unroll
        for (int i = 0; i < 4; ++i) {
            float* dst = &po[(n0 + 16 * i) * 100 + h * 16 + d0];
            *reinterpret_cast<float4*>(dst) =
                make_float4(acc[i][0], acc[i][1], acc[i][2], acc[i][3]);
            *reinterpret_cast<float4*>(dst + 4) =
                make_float4(acc[i][4], acc[i][5], acc[i][6], acc[i][7]);
        }
    }
    __syncthreads();

    if (tid < 192) {
        const int tt = tid & 15;
        const int r0 = (tid >> 4) << 3;
        float acc[4][8];
        #pragma unroll
        for (int i = 0; i < 4; ++i)
            #pragma unroll
            for (int j = 0; j < 8; ++j) acc[i][j] = 0.f;
        #pragma unroll 2
        for (int c0 = 0; c0 < 96; c0 += 4) {
            float4 xv[4];
            #pragma unroll
            for (int i = 0; i < 4; ++i) xv[i] = ld4s(&po[(tt + 16 * i) * 100 + c0]);
            #pragma unroll
            for (int j = 0; j < 8; ++j) {
                const float4 wv = ld4s(&proj_w[(r0 + j) * 96 + c0]);
                #pragma unroll
                for (int i = 0; i < 4; ++i) {
                    acc[i][j] += xv[i].x * wv.x + xv[i].y * wv.y
                               + xv[i].z * wv.z + xv[i].w * wv.w;
                }
            }
        }
        const float4 b0 = ld4s(&proj_b[r0]);
        const float4 b1 = ld4s(&proj_b[r0 + 4]);
        #pragma unroll
        for (int i = 0; i < 4; ++i) {
            const int t = tt + 16 * i;
            float* dst = &g_y[(win * 64 + t) * 96 + r0];
            *reinterpret_cast<float4*>(dst) =
                make_float4(acc[i][0] + b0.x, acc[i][1] + b0.y, acc[i][2] + b0.z, acc[i][3] + b0.w);
            *reinterpret_cast<float4*>(dst + 4) =
                make_float4(acc[i][4] + b1.x, acc[i][5] + b1.y, acc[i][6] + b1.z, acc[i][7] + b1.w);
        }
    }
}

// ============================================================================
// Kernel D: window reverse + un-shift + residual + LayerNorm2 -> transposed out
// ============================================================================
__global__ void k_res_ln2(const float* __restrict__ x,
                          const float* __restrict__ n2w,
                          const float* __restrict__ n2b) {
    __shared__ float s[CC * 65];
    const int h = blockIdx.y;
    const int w0 = blockIdx.x * 64;
    const int t = threadIdx.x;

    #pragma unroll 4
    for (int c = 0; c < CC; ++c)
        s[c * 65 + t] = x[c * HWSZ + h * WW + w0 + t];
    __syncthreads();

    for (int idx = t; idx < 64 * CC; idx += 64) {
        const int tt = idx / CC, c = idx - tt * CC;
        const int wp = w0 + tt;
        const int hs = (h - SHIFT) & (HH - 1);
        const int ws = (wp - SHIFT) & (WW - 1);
        const int base = (((hs >> 3) * 64 + (ws >> 3)) * NTOK + ((hs & 7) << 3) + (ws & 7)) * CC;
        s[c * 65 + tt] += g_y[base + c];
    }
    __syncthreads();

    float mu = 0.f;
    #pragma unroll 8
    for (int c = 0; c < CC; ++c) mu += s[c * 65 + t];
    mu *= (1.0f / CC);
    float var = 0.f;
    #pragma unroll 8
    for (int c = 0; c < CC; ++c) { float d = s[c * 65 + t] - mu; var += d * d; }
    var *= (1.0f / CC);
    const float rstd = rsqrtf(var + EPS);

    const int p = h * WW + w0 + t;
    #pragma unroll 4
    for (int c = 0; c < CC; ++c) {
        const float v = s[c * 65 + t];
        g_x1T[c * HWSZ + p] = v;
        g_hnT[c * HWSZ + p] = (v - mu) * rstd * n2w[c] + n2b[c];
    }
}

// ============================================================================
// Kernel E: MLP via mma.sync bf16 split-precision (hi+lo, 3 MMA terms).
// 2048 CTAs x 256 threads (8 warps), 128 pixels per CTA.
//
// smem layout (bytes, bf16 elements with padded row strides):
//   A1 (X, 128x96, stride 104):   hi @ 0      lo @ 26624
//   W  (shared W1/W2 chunk buf):  hi @ 53248  lo @ 79872    (26624 each)
//   A2 (GELU out, 128x128, 136):  hi @ 106496 lo @ 141312   (34816 each)
// total 176128 B
// ============================================================================
#define OFF_A1H 0
#define OFF_A1L 26624
#define OFF_WH  53248
#define OFF_WL  79872
#define OFF_A2H 106496
#define OFF_A2L 141312
#define SMEM_MLP 176128

__global__ __launch_bounds__(256, 1)
void k_mlp_mma(const float* __restrict__ fc1_w,
               const float* __restrict__ fc1_b,
               const float* __restrict__ fc2_w,
               const float* __restrict__ fc2_b,
               float* __restrict__ out) {
    extern __shared__ char smc[];
    const int tid = threadIdx.x;
    const int wid = tid >> 5;
    const int lane = tid & 31;
    const int g = lane >> 2;       // 0..7
    const int tg = lane & 3;       // 0..3
    const int p0 = blockIdx.x * 128;
    const int m0 = wid * 16;       // warp's M rows

    // ---- stage A1 = LN2 output as bf16 hi/lo, [tok][c], stride 104 ----
    for (int i = tid; i < 128 * 48; i += 256) {
        const int p = i & 127;
        const int c0 = (i >> 7) << 1;
        const float v0 = g_hnT[c0 * HWSZ + p0 + p];
        const float v1 = g_hnT[(c0 + 1) * HWSZ + p0 + p];
        unsigned short h0, l0, h1, l1;
        bf16_split(v0, h0, l0);
        bf16_split(v1, h1, l1);
        *(u32*)(smc + OFF_A1H + (p * 104 + c0) * 2) = pack2(h0, h1);
        *(u32*)(smc + OFF_A1L + (p * 104 + c0) * 2) = pack2(l0, l1);
    }

    float acc2[12][4];
    #pragma unroll
    for (int nt = 0; nt < 12; ++nt)
        #pragma unroll
        for (int q = 0; q < 4; ++q) acc2[nt][q] = 0.f;

    for (int nc = 0; nc < 3; ++nc) {
        __syncthreads();   // W buffer free (prev chunk GEMM2 readers done); A1 ready (nc=0)

        // ---- load W1 chunk: rows n = nc*128..+127, cols k 0..95, stride 104 ----
        for (int i = tid; i < 128 * 48; i += 256) {
            const int r = i / 48;
            const int c0 = (i - r * 48) << 1;
            const float* wp = &fc1_w[(nc * 128 + r) * 96 + c0];
            unsigned short h0, l0, h1, l1;
            bf16_split(wp[0], h0, l0);
            bf16_split(wp[1], h1, l1);
            *(u32*)(smc + OFF_WH + (r * 104 + c0) * 2) = pack2(h0, h1);
            *(u32*)(smc + OFF_WL + (r * 104 + c0) * 2) = pack2(l0, l1);
        }
        __syncthreads();

        // ---- GEMM1 chunk: D1[m0..+15][0..127] ----
        float acc1[16][4];
        #pragma unroll
        for (int nt = 0; nt < 16; ++nt)
            #pragma unroll
            for (int q = 0; q < 4; ++q) acc1[nt][q] = 0.f;

        #pragma unroll
        for (int ks = 0; ks < 6; ++ks) {
            const int k0 = ks * 16;
            const int ra = (m0 + g) * 104 + k0 + tg * 2;
            u32 ah0 = *(u32*)(smc + OFF_A1H + ra * 2);
            u32 ah1 = *(u32*)(smc + OFF_A1H + (ra + 8 * 104) * 2);
            u32 ah2 = *(u32*)(smc + OFF_A1H + (ra + 8) * 2);
            u32 ah3 = *(u32*)(smc + OFF_A1H + (ra + 8 * 104 + 8) * 2);
            u32 al0 = *(u32*)(smc + OFF_A1L + ra * 2);
            u32 al1 = *(u32*)(smc + OFF_A1L + (ra + 8 * 104) * 2);
            u32 al2 = *(u32*)(smc + OFF_A1L + (ra + 8) * 2);
            u32 al3 = *(u32*)(smc + OFF_A1L + (ra + 8 * 104 + 8) * 2);
            #pragma unroll
            for (int nt = 0; nt < 16; ++nt) {
                const int rb = (nt * 8 + g) * 104 + k0 + tg * 2;
                u32 bh0 = *(u32*)(smc + OFF_WH + rb * 2);
                u32 bh1 = *(u32*)(smc + OFF_WH + (rb + 8) * 2);
                u32 bl0 = *(u32*)(smc + OFF_WL + rb * 2);
                u32 bl1 = *(u32*)(smc + OFF_WL + (rb + 8) * 2);
                mma_bf16(acc1[nt], ah0, ah1, ah2, ah3, bh0, bh1);
                mma_bf16(acc1[nt], ah0, ah1, ah2, ah3, bl0, bl1);
                mma_bf16(acc1[nt], al0, al1, al2, al3, bh0, bh1);
            }
        }

        // ---- bias + GELU + split -> A2 (own rows, no race) ----
        #pragma unroll
        for (int nt = 0; nt < 16; ++nt) {
            const int jb = nc * 128 + nt * 8 + tg * 2;
            const float bv0 = fc1_b[jb], bv1 = fc1_b[jb + 1];
            float x0 = acc1[nt][0] + bv0;
            float x1 = acc1[nt][1] + bv1;
            float y0 = acc1[nt][2] + bv0;
            float y1 = acc1[nt][3] + bv1;
            x0 = 0.5f * x0 * (1.0f + erff(x0 * 0.70710678118654752f));
            x1 = 0.5f * x1 * (1.0f + erff(x1 * 0.70710678118654752f));
            y0 = 0.5f * y0 * (1.0f + erff(y0 * 0.70710678118654752f));
            y1 = 0.5f * y1 * (1.0f + erff(y1 * 0.70710678118654752f));
            unsigned short h0, l0, h1, l1;
            const int col = nt * 8 + tg * 2;
            bf16_split(x0, h0, l0); bf16_split(x1, h1, l1);
            *(u32*)(smc + OFF_A2H + ((m0 + g) * 136 + col) * 2) = pack2(h0, h1);
            *(u32*)(smc + OFF_A2L + ((m0 + g) * 136 + col) * 2) = pack2(l0, l1);
            bf16_split(y0, h0, l0); bf16_split(y1, h1, l1);
            *(u32*)(smc + OFF_A2H + ((m0 + g + 8) * 136 + col) * 2) = pack2(h0, h1);
            *(u32*)(smc + OFF_A2L + ((m0 + g + 8) * 136 + col) * 2) = pack2(l0, l1);
        }
        __syncthreads();   // GEMM1 readers done with W; A2 writes complete

        // ---- load W2 chunk: rows n = 0..95, cols k = nc*128..+127, stride 136 ----
        for (int i = tid; i < 96 * 64; i += 256) {
            const int r = i >> 6;
            const int c0 = (i & 63) << 1;
            const float* wp = &fc2_w[r * 384 + nc * 128 + c0];
            unsigned short h0, l0, h1, l1;
            bf16_split(wp[0], h0, l0);
            bf16_split(wp[1], h1, l1);
            *(u32*)(smc + OFF_WH + (r * 136 + c0) * 2) = pack2(h0, h1);
            *(u32*)(smc + OFF_WL + (r * 136 + c0) * 2) = pack2(l0, l1);
        }
        __syncthreads();

        // ---- GEMM2 partial: acc2 += A2 @ W2chunk^T ----
        #pragma unroll
        for (int ks = 0; ks < 8; ++ks) {
            const int k0 = ks * 16;
            const int ra = (m0 + g) * 136 + k0 + tg * 2;
            u32 ah0 = *(u32*)(smc + OFF_A2H + ra * 2);
            u32 ah1 = *(u32*)(smc + OFF_A2H + (ra + 8 * 136) * 2);
            u32 ah2 = *(u32*)(smc + OFF_A2H + (ra + 8) * 2);
            u32 ah3 = *(u32*)(smc + OFF_A2H + (ra + 8 * 136 + 8) * 2);
            u32 al0 = *(u32*)(smc + OFF_A2L + ra * 2);
            u32 al1 = *(u32*)(smc + OFF_A2L + (ra + 8 * 136) * 2);
            u32 al2 = *(u32*)(smc + OFF_A2L + (ra + 8) * 2);
            u32 al3 = *(u32*)(smc + OFF_A2L + (ra + 8 * 136 + 8) * 2);
            #pragma unroll
            for (int nt = 0; nt < 12; ++nt) {
                const int rb = (nt * 8 + g) * 136 + k0 + tg * 2;
                u32 bh0 = *(u32*)(smc + OFF_WH + rb * 2);
                u32 bh1 = *(u32*)(smc + OFF_WH + (rb + 8) * 2);
                u32 bl0 = *(u32*)(smc + OFF_WL + rb * 2);
                u32 bl1 = *(u32*)(smc + OFF_WL + (rb + 8) * 2);
                mma_bf16(acc2[nt], ah0, ah1, ah2, ah3, bh0, bh1);
                mma_bf16(acc2[nt], ah0, ah1, ah2, ah3, bl0, bl1);
                mma_bf16(acc2[nt], al0, al1, al2, al3, bh0, bh1);
            }
        }
    }

    // ---- epilogue: + bias + residual -> NCHW out ----
    const int pA = p0 + m0 + g;
    const int pB = pA + 8;
    #pragma unroll
    for (int nt = 0; nt < 12; ++nt) {
        const int r0c = nt * 8 + tg * 2;
        const float b0v = fc2_b[r0c], b1v = fc2_b[r0c + 1];
        out[r0c * HWSZ + pA]       = acc2[nt][0] + b0v + g_x1T[r0c * HWSZ + pA];
        out[(r0c + 1) * HWSZ + pA] = acc2[nt][1] + b1v + g_x1T[(r0c + 1) * HWSZ + pA];
        out[r0c * HWSZ + pB]       = acc2[nt][2] + b0v + g_x1T[r0c * HWSZ + pB];
        out[(r0c + 1) * HWSZ + pB] = acc2[nt][3] + b1v + g_x1T[(r0c + 1) * HWSZ + pB];
    }
}

// ============================================================================
extern "C" void kernel_launch(void* const* d_in, const int* in_sizes, int n_in,
                              void* d_out, int out_size) {
    const float* x      = (const float*)d_in[0];
    const float* n1w    = (const float*)d_in[1];
    const float* n1b    = (const float*)d_in[2];
    const float* qkv_w  = (const float*)d_in[3];
    const float* qkv_b  = (const float*)d_in[4];
    const float* rpb    = (const float*)d_in[5];
    const float* proj_w = (const float*)d_in[6];
    const float* proj_b = (const float*)d_in[7];
    const float* n2w    = (const float*)d_in[8];
    const float* n2b    = (const float*)d_in[9];
    const float* fc1_w  = (const float*)d_in[10];
    const float* fc1_b  = (const float*)d_in[11];
    const float* fc2_w  = (const float*)d_in[12];
    const float* fc2_b  = (const float*)d_in[13];
    float* out = (float*)d_out;

    cudaFuncSetAttribute(k_attn,    cudaFuncAttributeMaxDynamicSharedMemorySize, 204800);
    cudaFuncSetAttribute(k_mlp_mma, cudaFuncAttributeMaxDynamicSharedMemorySize, SMEM_MLP);

    k_ln1_window<<<dim3(8, 512), 64>>>(x, n1w, n1b);
    k_attn<<<NWIN, 256, 204800>>>(qkv_w, qkv_b, rpb, proj_w, proj_b);
    k_res_ln2<<<dim3(8, 512), 64>>>(x, n2w, n2b);
    k_mlp_mma<<<HWSZ / 128, 256, SMEM_MLP>>>(fc1_w, fc1_b, fc2_w, fc2_b, out);
}